// round 1
// baseline (speedup 1.0000x reference)
#include <cuda_runtime.h>

#define BN 24
#define BM 128
#define BK 64
#define NITER 8
#define NFIX 12
#define NACT 12
#define EPSF 1e-8f
#define PIF 3.14159274101257324f   // float32(np.pi)

__device__ float g_G[BN * BN];   // G = S S^T, computed once per launch

// ---------------------------------------------------------------------------
// Pre-kernel: G[i][j] = dot(S[i,:], S[j,:]) over M=128
// ---------------------------------------------------------------------------
__global__ void compute_G_kernel(const float* __restrict__ S) {
    int t = blockIdx.x * blockDim.x + threadIdx.x;
    if (t < BN * BN) {
        int i = t / BN, j = t % BN;
        const float* si = S + i * BM;
        const float* sj = S + j * BM;
        float acc = 0.0f;
#pragma unroll 8
        for (int m = 0; m < BM; m++) acc += si[m] * sj[m];
        g_G[t] = acc;
    }
}

// ---------------------------------------------------------------------------
// Warp-wide sum (32 lanes, butterfly)
// ---------------------------------------------------------------------------
__device__ __forceinline__ float warpsum(float v) {
    v += __shfl_xor_sync(0xffffffffu, v, 16);
    v += __shfl_xor_sync(0xffffffffu, v, 8);
    v += __shfl_xor_sync(0xffffffffu, v, 4);
    v += __shfl_xor_sync(0xffffffffu, v, 2);
    v += __shfl_xor_sync(0xffffffffu, v, 1);
    return v;
}

__device__ __forceinline__ float out_angle(float co) {
    float c = fminf(fmaxf(-co, -1.0f + 1e-6f), 1.0f - 1e-6f);
    return acosf(c) / PIF;
}

// ---------------------------------------------------------------------------
// Main kernel: one warp per batch element b.
// Lane owns components k = 2*lane, 2*lane+1 of every K=64 vector.
// ---------------------------------------------------------------------------
__global__ void __launch_bounds__(32) mix_kernel(
    const float* __restrict__ z,
    const float* __restrict__ Vr,
    const int* __restrict__ isin,
    float* __restrict__ out)
{
    __shared__ float Gs[BN * BN];
    __shared__ float zsh[BN];
    __shared__ int   insh[BN];
    __shared__ float Vs[BN * BK];   // generic-path state only

    const int b    = blockIdx.x;
    const int lane = threadIdx.x;

    for (int idx = lane; idx < BN * BN; idx += 32) Gs[idx] = g_G[idx];
    if (lane < BN) {
        zsh[lane]  = z[b * BN + lane];
        insh[lane] = isin[b * BN + lane];
    }
    __syncwarp();

    unsigned mask = 0;
#pragma unroll
    for (int n = 0; n < BN; n++) if (insh[n] > 0) mask |= (1u << n);

    const float2* vr2  = (const float2*)Vr + (size_t)b * BN * (BK / 2);
    float*        outb = out + (size_t)b * BN;

    // ---- row 0 -> v0 ----
    float2 f0  = vr2[lane];
    float  ss0 = warpsum(f0.x * f0.x + f0.y * f0.y);
    float  in0 = 1.0f / (sqrtf(ss0) + EPSF);
    float  v0x = f0.x * in0, v0y = f0.y * in0;

    if (mask == 0xFFFu) {
        // ===================== FAST PATH: inputs = rows 0..11 ================
        float hx[NACT], hy[NACT];
        float Ax[NACT], Ay[NACT];

        // row 0 (fixed at v0): output + h contribution
        {
            float co = warpsum(v0x * v0x + v0y * v0y);
            if (lane == 0) outb[0] = out_angle(co);
        }
#pragma unroll
        for (int ii = 0; ii < NACT; ii++) {
            float w = Gs[(NFIX + ii) * BN + 0];
            hx[ii] = w * v0x;
            hy[ii] = w * v0y;
        }

        // rows 1..23: build V, fold fixed rows into h, emit fixed outputs
#pragma unroll
        for (int n = 1; n < BN; n++) {
            float2 f  = vr2[n * (BK / 2) + lane];
            float  ss = warpsum(f.x * f.x + f.y * f.y);
            float  iv = 1.0f / (sqrtf(ss) + EPSF);
            float  rx = f.x * iv, ry = f.y * iv;
            if (n < NFIX) {
                float pr = warpsum(rx * v0x + ry * v0y);
                float ux = rx - pr * v0x, uy = ry - pr * v0y;
                float uu = warpsum(ux * ux + uy * uy);
                float iu = 1.0f / (sqrtf(uu) + EPSF);
                ux *= iu; uy *= iu;
                float zz = zsh[n];
                float cz = cosf(PIF * zz), sz = sinf(PIF * zz);
                float vx = -cz * v0x + sz * ux;
                float vy = -cz * v0y + sz * uy;
                float co = warpsum(vx * v0x + vy * v0y);
                if (lane == 0) outb[n] = out_angle(co);
#pragma unroll
                for (int ii = 0; ii < NACT; ii++) {
                    float w = Gs[(NFIX + ii) * BN + n];
                    hx[ii] += w * vx;
                    hy[ii] += w * vy;
                }
            } else {
                Ax[n - NFIX] = rx;
                Ay[n - NFIX] = ry;
            }
        }

        // ---- 8 Gauss–Seidel sweeps over the 12 active rows ----
        for (int t = 0; t < NITER; t++) {
#pragma unroll
            for (int ii = 0; ii < NACT; ii++) {
                const int i = NFIX + ii;
                const float4* grow = (const float4*)&Gs[i * BN + NFIX];
                float4 w0 = grow[0], w1 = grow[1], w2 = grow[2];
                float wv[NACT] = { w0.x, w0.y, w0.z, w0.w,
                                   w1.x, w1.y, w1.z, w1.w,
                                   w2.x, w2.y, w2.z, w2.w };
                float ax = hx[ii], ay = hy[ii];
#pragma unroll
                for (int jj = 0; jj < NACT; jj++) {
                    ax += wv[jj] * Ax[jj];
                    ay += wv[jj] * Ay[jj];
                }
                // remove the n == i term
                ax -= wv[ii] * Ax[ii];
                ay -= wv[ii] * Ay[ii];

                float s   = warpsum(ax * ax + ay * ay);
                float inv = -1.0f / (sqrtf(s) + EPSF);
                Ax[ii] = ax * inv;
                Ay[ii] = ay * inv;
            }
        }

        // active-row outputs
#pragma unroll
        for (int ii = 0; ii < NACT; ii++) {
            float co = warpsum(Ax[ii] * v0x + Ay[ii] * v0y);
            if (lane == 0) outb[NFIX + ii] = out_angle(co);
        }
    } else {
        // ===================== GENERIC PATH (any mask) =======================
        Vs[0 * BK + 2 * lane]     = v0x;
        Vs[0 * BK + 2 * lane + 1] = v0y;
        for (int n = 1; n < BN; n++) {
            float2 f  = vr2[n * (BK / 2) + lane];
            float  ss = warpsum(f.x * f.x + f.y * f.y);
            float  iv = 1.0f / (sqrtf(ss) + EPSF);
            float  rx = f.x * iv, ry = f.y * iv;
            float pr = warpsum(rx * v0x + ry * v0y);
            float ux = rx - pr * v0x, uy = ry - pr * v0y;
            float uu = warpsum(ux * ux + uy * uy);
            float iu = 1.0f / (sqrtf(uu) + EPSF);
            ux *= iu; uy *= iu;
            float zz = zsh[n];
            float cz = cosf(PIF * zz), sz = sinf(PIF * zz);
            bool  inp = insh[n] > 0;
            Vs[n * BK + 2 * lane]     = inp ? (-cz * v0x + sz * ux) : rx;
            Vs[n * BK + 2 * lane + 1] = inp ? (-cz * v0y + sz * uy) : ry;
        }
        __syncwarp();
        for (int t = 0; t < NITER; t++) {
            for (int i = 0; i < BN; i++) {
                if (insh[i] > 0) continue;
                float ax = 0.0f, ay = 0.0f;
                for (int n = 0; n < BN; n++) {
                    float w = Gs[i * BN + n];
                    ax += w * Vs[n * BK + 2 * lane];
                    ay += w * Vs[n * BK + 2 * lane + 1];
                }
                float wd = Gs[i * BN + i];
                ax -= wd * Vs[i * BK + 2 * lane];
                ay -= wd * Vs[i * BK + 2 * lane + 1];
                float s   = warpsum(ax * ax + ay * ay);
                float inv = -1.0f / (sqrtf(s) + EPSF);
                Vs[i * BK + 2 * lane]     = ax * inv;
                Vs[i * BK + 2 * lane + 1] = ay * inv;
                __syncwarp();
            }
        }
        for (int n = 0; n < BN; n++) {
            float co = warpsum(Vs[n * BK + 2 * lane] * v0x +
                               Vs[n * BK + 2 * lane + 1] * v0y);
            if (lane == 0) outb[n] = out_angle(co);
        }
    }
}

// ---------------------------------------------------------------------------
extern "C" void kernel_launch(void* const* d_in, const int* in_sizes, int n_in,
                              void* d_out, int out_size) {
    const float* z    = (const float*)d_in[0];   // (B, 24)
    const float* S    = (const float*)d_in[1];   // (24, 128)
    const float* Vr   = (const float*)d_in[2];   // (B, 24, 64)
    const int*   isin = (const int*)d_in[3];     // (B, 24)
    float*       out  = (float*)d_out;           // (B, 24)

    const int B = in_sizes[0] / BN;

    compute_G_kernel<<<(BN * BN + 127) / 128, 128>>>(S);
    mix_kernel<<<B, 32>>>(z, Vr, isin, out);
}

// round 2
// speedup vs baseline: 2.5108x; 2.5108x over previous
#include <cuda_runtime.h>

#define BN 24
#define BM 128
#define BK 64
#define NITER 8
#define NFIX 12
#define NACT 12
#define PIF 3.14159274101257324f   // float32(np.pi)
#define BLOCK 128
#define GPB (BLOCK / 16)           // 8 batches (16-lane groups) per block

// ---------------------------------------------------------------------------
// float4 helpers
// ---------------------------------------------------------------------------
__device__ __forceinline__ float dot4(float4 a, float4 b) {
    return fmaf(a.x, b.x, fmaf(a.y, b.y, fmaf(a.z, b.z, a.w * b.w)));
}
__device__ __forceinline__ float4 mul4(float4 a, float s) {
    return make_float4(a.x * s, a.y * s, a.z * s, a.w * s);
}
__device__ __forceinline__ float4 add4(float4 a, float4 b) {
    return make_float4(a.x + b.x, a.y + b.y, a.z + b.z, a.w + b.w);
}
// a*s + c
__device__ __forceinline__ float4 fma4(float4 a, float s, float4 c) {
    return make_float4(fmaf(a.x, s, c.x), fmaf(a.y, s, c.y),
                       fmaf(a.z, s, c.z), fmaf(a.w, s, c.w));
}

// sum across the 16-lane subgroup (xor 8,4,2,1 stays inside the group)
__device__ __forceinline__ float gsum16(float v) {
    v += __shfl_xor_sync(0xffffffffu, v, 8);
    v += __shfl_xor_sync(0xffffffffu, v, 4);
    v += __shfl_xor_sync(0xffffffffu, v, 2);
    v += __shfl_xor_sync(0xffffffffu, v, 1);
    return v;
}
// two sums at once (independent butterflies overlap latency)
__device__ __forceinline__ void gsum16_2(float& a, float& b) {
    a += __shfl_xor_sync(0xffffffffu, a, 8); b += __shfl_xor_sync(0xffffffffu, b, 8);
    a += __shfl_xor_sync(0xffffffffu, a, 4); b += __shfl_xor_sync(0xffffffffu, b, 4);
    a += __shfl_xor_sync(0xffffffffu, a, 2); b += __shfl_xor_sync(0xffffffffu, b, 2);
    a += __shfl_xor_sync(0xffffffffu, a, 1); b += __shfl_xor_sync(0xffffffffu, b, 1);
}

__device__ __forceinline__ float out_angle(float co) {
    float c = fminf(fmaxf(-co, -1.0f + 1e-6f), 1.0f - 1e-6f);
    return acosf(c) / PIF;
}

// ---------------------------------------------------------------------------
// One 16-lane group per batch element; lane owns comps 4*gl .. 4*gl+3.
// ---------------------------------------------------------------------------
__global__ void __launch_bounds__(BLOCK) mix_kernel(
    const float* __restrict__ z,
    const float* __restrict__ S,
    const float* __restrict__ Vr,
    const int* __restrict__ isin,
    float* __restrict__ out,
    int B)
{
    __shared__ __align__(16) float Gs[BN * BN];
    __shared__ float Ssh[BM * BN];     // transposed: Ssh[m*BN + i] = S[i][m]

    const int tid = threadIdx.x;

    // ---- phase 0: G = S S^T computed per block (removes separate kernel) ----
    for (int idx = tid; idx < BN * BM; idx += BLOCK) {
        int i = idx / BM, m = idx % BM;
        Ssh[m * BN + i] = S[idx];
    }
    __syncthreads();
    for (int e = tid; e < BN * BN; e += BLOCK) {
        int i = e / BN, j = e % BN;
        float acc = 0.0f;
#pragma unroll 8
        for (int m = 0; m < BM; m++)
            acc = fmaf(Ssh[m * BN + i], Ssh[m * BN + j], acc);
        Gs[e] = acc;
    }
    __syncthreads();

    const int grp = tid >> 4;
    const int gl  = tid & 15;
    int b = blockIdx.x * GPB + grp;
    if (b >= B) b = B - 1;   // duplicate work, same values -> deterministic

    const float4* vrow = (const float4*)Vr + (size_t)b * BN * (BK / 4);
    float*        outb = out + (size_t)b * BN;

    unsigned mask = 0;
#pragma unroll
    for (int n = 0; n < BN; n++)
        mask |= (isin[b * BN + n] > 0) ? (1u << n) : 0u;

    // ---- v0 ----
    float4 f0  = vrow[gl];
    float  ss0 = gsum16(dot4(f0, f0));
    float4 v0  = mul4(f0, rsqrtf(fmaxf(ss0, 1e-30f)));

    if (mask == 0xFFFu) {
        // ================= FAST PATH: inputs are rows 0..11 =================
        float co0 = gsum16(dot4(v0, v0));     // |v0|^2, also row-0 output
        if (gl == 0) outb[0] = out_angle(co0);
        const float nv0 = co0;

        float4 h[NACT];
#pragma unroll
        for (int ii = 0; ii < NACT; ii++)
            h[ii] = mul4(v0, Gs[(NFIX + ii) * BN + 0]);

        // fixed input rows 1..11: build V_in, emit outputs, fold into h
#pragma unroll
        for (int n = 1; n < NFIX; n++) {
            float4 f  = vrow[n * 16 + gl];
            float  ss = dot4(f, f);
            float  fv = dot4(f, v0);
            gsum16_2(ss, fv);
            // |f - fv*v0|^2 = ss - fv^2 (2 - |v0|^2)
            float ww = fmaf(-fv * fv, 2.0f - nv0, ss);
            float iu = rsqrtf(fmaxf(ww, 1e-24f));
            float4 u = mul4(fma4(v0, -fv, f), iu);
            float sz, cz;
            __sincosf(PIF * z[b * BN + n], &sz, &cz);
            float4 vv = fma4(v0, -cz, mul4(u, sz));
            float co = gsum16(dot4(vv, v0));
            if (gl == 0) outb[n] = out_angle(co);
#pragma unroll
            for (int ii = 0; ii < NACT; ii++)
                h[ii] = fma4(vv, Gs[(NFIX + ii) * BN + n], h[ii]);
        }

        // free rows 12..23: normalized random init
        float4 A[NACT];
#pragma unroll
        for (int jj = 0; jj < NACT; jj++) {
            float4 f  = vrow[(NFIX + jj) * 16 + gl];
            float  ss = gsum16(dot4(f, f));
            A[jj] = mul4(f, rsqrtf(fmaxf(ss, 1e-30f)));
        }

        // ---- 8 Gauss–Seidel sweeps over 12 active rows ----
        for (int t = 0; t < NITER; t++) {
#pragma unroll
            for (int ii = 0; ii < NACT; ii++) {
                const float4* gr = (const float4*)&Gs[(NFIX + ii) * BN + NFIX];
                float4 w0 = gr[0], w1 = gr[1], w2 = gr[2];
                const float wv[NACT] = { w0.x, w0.y, w0.z, w0.w,
                                         w1.x, w1.y, w1.z, w1.w,
                                         w2.x, w2.y, w2.z, w2.w };
                float4 a0 = h[ii];
                float4 a1 = make_float4(0.f, 0.f, 0.f, 0.f);
#pragma unroll
                for (int jj = 0; jj < NACT; jj++) {
                    if (jj == ii) continue;
                    if (jj & 1) a1 = fma4(A[jj], wv[jj], a1);
                    else        a0 = fma4(A[jj], wv[jj], a0);
                }
                float4 g = add4(a0, a1);
                float  s = gsum16(dot4(g, g));
                A[ii] = mul4(g, -rsqrtf(fmaxf(s, 1e-30f)));
            }
        }

        // active outputs
#pragma unroll
        for (int ii = 0; ii < NACT; ii++) {
            float co = gsum16(dot4(A[ii], v0));
            if (gl == 0) outb[NFIX + ii] = out_angle(co);
        }
    } else {
        // ============ GENERIC PATH (any mask) — cold, local-memory OK ========
        float4 Vl[BN];
        Vl[0] = v0;
        float nv0g = gsum16(dot4(v0, v0));
#pragma unroll 1
        for (int n = 1; n < BN; n++) {
            float4 f  = vrow[n * 16 + gl];
            float  ss = dot4(f, f);
            float  fv = dot4(f, v0);
            gsum16_2(ss, fv);
            float4 r = mul4(f, rsqrtf(fmaxf(ss, 1e-30f)));
            if ((mask >> n) & 1u) {
                float ww = fmaf(-fv * fv, 2.0f - nv0g, ss);
                float iu = rsqrtf(fmaxf(ww, 1e-24f));
                float4 u = mul4(fma4(v0, -fv, f), iu);
                float sz, cz;
                __sincosf(PIF * z[b * BN + n], &sz, &cz);
                Vl[n] = fma4(v0, -cz, mul4(u, sz));
            } else {
                Vl[n] = r;
            }
        }
#pragma unroll 1
        for (int t = 0; t < NITER; t++) {
#pragma unroll 1
            for (int i = 0; i < BN; i++) {
                if ((mask >> i) & 1u) continue;
                float4 acc = make_float4(0.f, 0.f, 0.f, 0.f);
#pragma unroll 1
                for (int n = 0; n < BN; n++)
                    acc = fma4(Vl[n], Gs[i * BN + n], acc);
                acc = fma4(Vl[i], -Gs[i * BN + i], acc);
                float s = gsum16(dot4(acc, acc));
                Vl[i] = mul4(acc, -rsqrtf(fmaxf(s, 1e-30f)));
            }
        }
#pragma unroll 1
        for (int n = 0; n < BN; n++) {
            float co = gsum16(dot4(Vl[n], v0));
            if (gl == 0) outb[n] = out_angle(co);
        }
    }
}

// ---------------------------------------------------------------------------
extern "C" void kernel_launch(void* const* d_in, const int* in_sizes, int n_in,
                              void* d_out, int out_size) {
    const float* z    = (const float*)d_in[0];   // (B, 24)
    const float* S    = (const float*)d_in[1];   // (24, 128)
    const float* Vr   = (const float*)d_in[2];   // (B, 24, 64)
    const int*   isin = (const int*)d_in[3];     // (B, 24)
    float*       out  = (float*)d_out;           // (B, 24)

    const int B = in_sizes[0] / BN;
    const int grid = (B + GPB - 1) / GPB;
    mix_kernel<<<grid, BLOCK>>>(z, S, Vr, isin, out, B);
}